// round 1
// baseline (speedup 1.0000x reference)
#include <cuda_runtime.h>
#include <cstdint>

#define H      100
#define NBATCH 4096
#define SEQ    512
#define TB     32
#define NBLK   (NBATCH / TB)   // 128
#define NTHREADS 416           // 52 hp-groups * 8 batch-groups

// smem: Wp [100][2][104] float2 (type-paired, hu padded to 104)
//       Hd [2][104][32]  float2 (h duplicated (h,h), batch-interleaved, double buffered)
#define WP_F2 (100 * 2 * 104)  // 20800 float2
#define HD_F2 (104 * 32)       // 3328 float2 per buffer
#define SMEM_BYTES ((WP_F2 + 2 * HD_F2) * 8)  // 219,648 B

typedef unsigned long long u64;

__device__ __forceinline__ void fma2(u64 &d, u64 a, u64 b) {
    asm("fma.rn.f32x2 %0, %1, %2, %0;" : "+l"(d) : "l"(a), "l"(b));
}
__device__ __forceinline__ u64 pk(float x, float y) {
    u64 r; asm("mov.b64 %0, {%1, %2};" : "=l"(r) : "f"(x), "f"(y)); return r;
}
__device__ __forceinline__ float2 upk(u64 v) {
    float2 r; asm("mov.b64 {%0, %1}, %2;" : "=f"(r.x), "=f"(r.y) : "l"(v)); return r;
}
__device__ __forceinline__ float sigf(float v) {
    return __fdividef(1.0f, 1.0f + __expf(-v));
}
__device__ __forceinline__ float tanhfast(float v) {
    return __fdividef(2.0f, 1.0f + __expf(-2.0f * v)) - 1.0f;
}

__global__ void __launch_bounds__(NTHREADS, 1)
lstm_kernel(const float* __restrict__ x,     // [512][4096]
            const float* __restrict__ Wih,   // [400]
            const float* __restrict__ Whh,   // [400][100]
            const float* __restrict__ bih,   // [400]
            const float* __restrict__ bhh,   // [400]
            const float* __restrict__ Wlin,  // [100]
            const float* __restrict__ blin,  // [1]
            float* __restrict__ out)         // [4096]
{
    extern __shared__ u64 sm[];
    u64* Wp = sm;            // [ (k*2 + tp) * 104 + hu ]
    u64* Hd = sm + WP_F2;    // [ buf*HD_F2 + k*32 + col ]

    const int tid = threadIdx.x;
    const int hp  = tid >> 3;   // 0..51 (hidden pair; hp>=50 is padding work)
    const int bg  = tid & 7;    // 0..7  (batch group of 4)

    // ---- Stage W_hh into type-paired smem layout ----
    // Wp[k][tp][hu] = ( W_hh[(2tp+0)*100+hu][k], W_hh[(2tp+1)*100+hu][k] )
    for (int idx = tid; idx < WP_F2; idx += NTHREADS) {
        int hu = idx % 104;
        int tp = (idx / 104) & 1;
        int k  = idx / 208;
        float wx = 0.f, wy = 0.f;
        if (hu < 100) {
            wx = Whh[((tp * 2 + 0) * 100 + hu) * 100 + k];
            wy = Whh[((tp * 2 + 1) * 100 + hu) * 100 + k];
        }
        Wp[idx] = pk(wx, wy);
    }
    // zero both h buffers (h0 = 0)
    for (int idx = tid; idx < 2 * HD_F2; idx += NTHREADS)
        Hd[idx] = 0ull;

    // ---- per-thread constants: bias sums and W_ih for my 8 gate rows ----
    float bs[8], wi[8];  // [u*4 + type], types: 0=i 1=f 2=g 3=o
    #pragma unroll
    for (int u = 0; u < 2; u++) {
        int hu = 2 * hp + u;
        #pragma unroll
        for (int ty = 0; ty < 4; ty++) {
            if (hu < 100) {
                int j = ty * 100 + hu;
                bs[u * 4 + ty] = bih[j] + bhh[j];
                wi[u * 4 + ty] = Wih[j];
            } else {
                bs[u * 4 + ty] = 0.f;
                wi[u * 4 + ty] = 0.f;
            }
        }
    }
    float c[8];  // cell state, [u*4 + i]
    #pragma unroll
    for (int q = 0; q < 8; q++) c[q] = 0.f;

    const int bbase = blockIdx.x * TB + bg * 4;
    __syncthreads();

    // ---- recurrence over 512 steps ----
    for (int t = 0; t < SEQ; t++) {
        const u64* hcur = Hd + ((t & 1) ? HD_F2 : 0);
        u64*       hnxt = Hd + ((t & 1) ? 0 : HD_F2);

        // x for my 4 batches (consumed only in epilogue -> latency hidden)
        float4 xv = *(const float4*)(x + (size_t)t * NBATCH + bbase);

        u64 accA[2][4], accB[2][4];  // accA[u][i] = (i,f) gates; accB = (g,o)
        #pragma unroll
        for (int u = 0; u < 2; u++)
            #pragma unroll
            for (int i = 0; i < 4; i++) { accA[u][i] = 0ull; accB[u][i] = 0ull; }

        #pragma unroll 5
        for (int k = 0; k < H; k++) {
            // W for hidden units 2hp, 2hp+1 : one LDS.128 per type-pair
            const ulonglong2 wA = *(const ulonglong2*)(Wp + (k * 2 + 0) * 104 + 2 * hp);
            const ulonglong2 wB = *(const ulonglong2*)(Wp + (k * 2 + 1) * 104 + 2 * hp);
            u64 hv[4];
            #pragma unroll
            for (int i = 0; i < 4; i++)
                hv[i] = hcur[k * 32 + i * 8 + bg];  // (h,h) for batch bg*4+i
            #pragma unroll
            for (int i = 0; i < 4; i++) {
                fma2(accA[0][i], wA.x, hv[i]);
                fma2(accA[1][i], wA.y, hv[i]);
                fma2(accB[0][i], wB.x, hv[i]);
                fma2(accB[1][i], wB.y, hv[i]);
            }
        }

        // ---- epilogue: gates -> activations -> c,h update ----
        #pragma unroll
        for (int u = 0; u < 2; u++) {
            int hu = 2 * hp + u;
            #pragma unroll
            for (int i = 0; i < 4; i++) {
                float xb = (i == 0) ? xv.x : (i == 1) ? xv.y : (i == 2) ? xv.z : xv.w;
                float2 aA = upk(accA[u][i]);  // (i_gate, f_gate) pre-act
                float2 aB = upk(accB[u][i]);  // (g_gate, o_gate) pre-act
                float gi = aA.x + bs[u * 4 + 0] + wi[u * 4 + 0] * xb;
                float gf = aA.y + bs[u * 4 + 1] + wi[u * 4 + 1] * xb;
                float gg = aB.x + bs[u * 4 + 2] + wi[u * 4 + 2] * xb;
                float go = aB.y + bs[u * 4 + 3] + wi[u * 4 + 3] * xb;
                float si = sigf(gi);
                float sf = sigf(gf);
                float so = sigf(go);
                float tg = tanhfast(gg);
                float cn = sf * c[u * 4 + i] + si * tg;
                c[u * 4 + i] = cn;
                float hn = so * tanhfast(cn);
                hnxt[hu * 32 + i * 8 + bg] = pk(hn, hn);
            }
        }
        __syncthreads();
    }

    // ---- linear head: out[b] = h_T[b] . W_lin + b_lin ----
    if (tid < TB) {
        const u64* hfin = Hd + ((SEQ & 1) ? HD_F2 : 0);  // SEQ even -> buffer 0
        int b = tid;
        int col = (b & 3) * 8 + (b >> 2);
        float acc = blin[0];
        #pragma unroll 4
        for (int k = 0; k < H; k++) {
            float2 hv = upk(hfin[k * 32 + col]);
            acc += hv.x * __ldg(Wlin + k);
        }
        out[blockIdx.x * TB + b] = acc;
    }
}

extern "C" void kernel_launch(void* const* d_in, const int* in_sizes, int n_in,
                              void* d_out, int out_size) {
    const float* x    = (const float*)d_in[0];
    const float* Wih  = (const float*)d_in[1];
    const float* Whh  = (const float*)d_in[2];
    const float* bih  = (const float*)d_in[3];
    const float* bhh  = (const float*)d_in[4];
    const float* Wlin = (const float*)d_in[5];
    const float* blin = (const float*)d_in[6];

    cudaFuncSetAttribute(lstm_kernel, cudaFuncAttributeMaxDynamicSharedMemorySize, SMEM_BYTES);
    lstm_kernel<<<NBLK, NTHREADS, SMEM_BYTES>>>(x, Wih, Whh, bih, bhh, Wlin, blin,
                                                (float*)d_out);
}